// round 1
// baseline (speedup 1.0000x reference)
#include <cuda_runtime.h>

#define BSZ 8192
#define TSTEPS 128
#define NN 25
// HID = 4, gates = 16

// Scratch (allocation-free rule: static __device__ arrays)
__device__ float g_xT[TSTEPS * NN * BSZ];       // [t][i][b]  ~105 MB
__device__ float g_H[BSZ * 200];                // final hidden concat, (bs, 200)

// ---------------------------------------------------------------------------
// Kernel 1: transpose x (bs, N, T) -> xT[t][i][b]
// ---------------------------------------------------------------------------
__global__ void transpose_kernel(const float* __restrict__ x) {
    __shared__ float tile[32][33];
    int i  = blockIdx.z;
    int b0 = blockIdx.x * 32;
    int t0 = blockIdx.y * 32;
    int tx = threadIdx.x, ty = threadIdx.y;
#pragma unroll
    for (int r = 0; r < 4; r++) {
        int b = b0 + ty + r * 8;
        int t = t0 + tx;
        tile[ty + r * 8][tx] = x[(b * NN + i) * TSTEPS + t];
    }
    __syncthreads();
#pragma unroll
    for (int r = 0; r < 4; r++) {
        int t = t0 + ty + r * 8;
        int b = b0 + tx;
        g_xT[(t * NN + i) * BSZ + b] = tile[tx][ty + r * 8];
    }
}

// ---------------------------------------------------------------------------
// Fast activations (MUFU EX2 + RCP based; ~1e-7 abs error)
// ---------------------------------------------------------------------------
__device__ __forceinline__ float sigf(float x) {
    return __fdividef(1.0f, 1.0f + __expf(-x));
}
__device__ __forceinline__ float tanh_fast(float x) {
    // 2*sigmoid(2x) - 1 ; saturates correctly for large |x|
    float s = __fdividef(1.0f, 1.0f + __expf(-2.0f * x));
    return fmaf(2.0f, s, -1.0f);
}

// ---------------------------------------------------------------------------
// Kernel 2: the grid-LSTM recurrence.
// 4 threads per (batch, direction) group; thread u owns hidden unit u.
// Thread u computes gate columns {u, 4+u, 8+u, 12+u}.
// Cross-unit communication via __shfl_sync within the 4-lane group.
// ---------------------------------------------------------------------------
__global__ __launch_bounds__(64) void rec_kernel(
    const float* __restrict__ h0f, const float* __restrict__ c0f,
    const float* __restrict__ h0b, const float* __restrict__ c0b,
    const float* __restrict__ Wxf, const float* __restrict__ Whf,
    const float* __restrict__ Wnf, const float* __restrict__ bf,
    const float* __restrict__ Wxb, const float* __restrict__ Whb,
    const float* __restrict__ Wnb, const float* __restrict__ bbk) {
    int tid = blockIdx.x * 64 + threadIdx.x;   // 0 .. 65535
    int u   = tid & 3;
    int gid = tid >> 2;                        // group = (dir, b)
    int b   = gid & (BSZ - 1);
    int dir = gid >> 13;                       // 0 = fwd, 1 = bwd

    const float* Wx = dir ? Wxb : Wxf;
    const float* Wh = dir ? Whb : Whf;
    const float* Wn = dir ? Wnb : Wnf;
    const float* bv = dir ? bbk : bf;
    const float* h0 = dir ? h0b : h0f;
    const float* c0 = dir ? c0b : c0f;

    // Per-thread weights: g=0:ig, 1:fg, 2:og, 3:cc ; column = g*4 + u
    float wx[4], bg[4], wh[4][4], wu[4], wd[4], wl[4], wr[4];
#pragma unroll
    for (int g = 0; g < 4; g++) {
        int col = g * 4 + u;
        wx[g] = Wx[col];
        bg[g] = bv[col];
#pragma unroll
        for (int j = 0; j < 4; j++) wh[j][g] = Wh[j * 16 + col];
        wu[g] = Wn[0 * 16 + col];
        wd[g] = Wn[1 * 16 + col];
        float w2 = Wn[2 * 16 + col];
        float w3 = Wn[3 * 16 + col];
        // fwd neighbor order [up,dn,lf,rt]; bwd order [up,dn,rt,lf]
        wl[g] = dir ? w3 : w2;
        wr[g] = dir ? w2 : w3;
    }

    float h[NN], c[NN];
#pragma unroll
    for (int i = 0; i < NN; i++) {
        h[i] = h0[(i * BSZ + b) * 4 + u];
        c[i] = c0[(i * BSZ + b) * 4 + u];
    }

#pragma unroll 1
    for (int t = 0; t < TSTEPS; t++) {
        int tt = dir ? (TSTEPS - 1 - t) : t;
        const float* xrow = g_xT + (tt * NN) * BSZ + b;
#pragma unroll
        for (int i = 0; i < NN; i++) {
            float xv = xrow[i * BSZ];
            float hv = h[i];
            float h0v = __shfl_sync(0xffffffffu, hv, 0, 4);
            float h1v = __shfl_sync(0xffffffffu, hv, 1, 4);
            float h2v = __shfl_sync(0xffffffffu, hv, 2, 4);
            float h3v = __shfl_sync(0xffffffffu, hv, 3, 4);

            float gg[4];
#pragma unroll
            for (int g = 0; g < 4; g++) {
                gg[g] = fmaf(xv, wx[g], bg[g]);
                gg[g] = fmaf(h0v, wh[0][g], gg[g]);
                gg[g] = fmaf(h1v, wh[1][g], gg[g]);
                gg[g] = fmaf(h2v, wh[2][g], gg[g]);
                gg[g] = fmaf(h3v, wh[3][g], gg[g]);
            }
            if (i >= 5) {   // up neighbor (updated this step)
                float nv = __shfl_sync(0xffffffffu, h[i - 5], 3, 4);
#pragma unroll
                for (int g = 0; g < 4; g++) gg[g] = fmaf(nv, wu[g], gg[g]);
            }
            if (i < 20) {   // down neighbor (previous step)
                float nv = __shfl_sync(0xffffffffu, h[i + 5], 3, 4);
#pragma unroll
                for (int g = 0; g < 4; g++) gg[g] = fmaf(nv, wd[g], gg[g]);
            }
            if (i >= 1) {   // left neighbor (updated this step, row-wrap)
                float nv = __shfl_sync(0xffffffffu, h[i - 1], 3, 4);
#pragma unroll
                for (int g = 0; g < 4; g++) gg[g] = fmaf(nv, wl[g], gg[g]);
            }
            if (i < 24) {   // right neighbor (previous step, row-wrap)
                float nv = __shfl_sync(0xffffffffu, h[i + 1], 3, 4);
#pragma unroll
                for (int g = 0; g < 4; g++) gg[g] = fmaf(nv, wr[g], gg[g]);
            }

            float si = sigf(gg[0]);
            float sf = sigf(gg[1]);
            float so = sigf(gg[2]);
            float tc = tanh_fast(gg[3]);
            float nc = fmaf(sf, c[i], si * tc);
            c[i] = nc;
            h[i] = so * tanh_fast(nc);
        }
    }

    // H[b, i*8 + dir*4 + u] = h[i]
#pragma unroll
    for (int i = 0; i < NN; i++) {
        g_H[b * 200 + i * 8 + dir * 4 + u] = h[i];
    }
}

// ---------------------------------------------------------------------------
// Kernel 3: FF head. 16 batch rows per block, 128 threads (one per neuron).
// ff = sigmoid(H @ W_ff + b_ff); out = softmax(ff @ W_out + b_out)
// ---------------------------------------------------------------------------
__global__ void ff_kernel(const float* __restrict__ Wff, const float* __restrict__ bff,
                          const float* __restrict__ Wout, const float* __restrict__ bout,
                          float* __restrict__ out) {
    __shared__ float Hs[16 * 200];
    __shared__ float Fs[16 * 128];
    int k  = threadIdx.x;        // neuron 0..127
    int b0 = blockIdx.x * 16;

    for (int idx = k; idx < 16 * 200; idx += 128)
        Hs[idx] = g_H[b0 * 200 + idx];
    __syncthreads();

    float acc[16];
    float bk = bff[k];
#pragma unroll
    for (int m = 0; m < 16; m++) acc[m] = bk;
#pragma unroll 4
    for (int j = 0; j < 200; j++) {
        float w = Wff[j * 128 + k];
#pragma unroll
        for (int m = 0; m < 16; m++) acc[m] = fmaf(Hs[m * 200 + j], w, acc[m]);
    }
#pragma unroll
    for (int m = 0; m < 16; m++) Fs[m * 128 + k] = sigf(acc[m]);
    __syncthreads();

    if (k < 16) {
        float s0 = bout[0], s1 = bout[1];
#pragma unroll 4
        for (int j = 0; j < 128; j++) {
            float f = Fs[k * 128 + j];
            s0 = fmaf(f, Wout[j * 2 + 0], s0);
            s1 = fmaf(f, Wout[j * 2 + 1], s1);
        }
        // softmax over 2 logits == sigmoid of difference
        out[(b0 + k) * 2 + 0] = sigf(s0 - s1);
        out[(b0 + k) * 2 + 1] = sigf(s1 - s0);
    }
}

// ---------------------------------------------------------------------------
extern "C" void kernel_launch(void* const* d_in, const int* in_sizes, int n_in,
                              void* d_out, int out_size) {
    const float* x    = (const float*)d_in[0];
    const float* h0f  = (const float*)d_in[1];
    const float* c0f  = (const float*)d_in[2];
    const float* h0b  = (const float*)d_in[3];
    const float* c0b  = (const float*)d_in[4];
    const float* Wxf  = (const float*)d_in[5];
    const float* Whf  = (const float*)d_in[6];
    const float* Wnf  = (const float*)d_in[7];
    const float* bf   = (const float*)d_in[8];
    const float* Wxb  = (const float*)d_in[9];
    const float* Whb  = (const float*)d_in[10];
    const float* Wnb  = (const float*)d_in[11];
    const float* bb   = (const float*)d_in[12];
    const float* Wff  = (const float*)d_in[13];
    const float* bff  = (const float*)d_in[14];
    const float* Wout = (const float*)d_in[15];
    const float* bout = (const float*)d_in[16];

    transpose_kernel<<<dim3(BSZ / 32, TSTEPS / 32, NN), dim3(32, 8)>>>(x);
    rec_kernel<<<65536 / 64, 64>>>(h0f, c0f, h0b, c0b,
                                   Wxf, Whf, Wnf, bf,
                                   Wxb, Whb, Wnb, bb);
    ff_kernel<<<BSZ / 16, 128>>>(Wff, bff, Wout, bout, (float*)d_out);
}